// round 9
// baseline (speedup 1.0000x reference)
#include <cuda_runtime.h>
#include <cuda_bf16.h>
#include <mma.h>
#include <cstdint>

using namespace nvcuda;

#define T_ 8
#define N_ 50000
#define D_ 128
#define E_ 800000
#define L_ 2
#define SH_ 8
#define FH_ 16

// ---------------- scratch pool (static device memory; no allocs) ----------------
constexpr size_t BIG    = (size_t)T_ * N_ * D_;    // 51,200,000 floats
constexpr size_t SMALLV = (size_t)T_ * N_ * SH_;   // 3,200,000 floats
constexpr size_t RN     = (size_t)T_ * N_;         // 400,000 rows
constexpr size_t OFF_H    = 0;
constexpr size_t OFF_TI   = BIG;
constexpr size_t OFF_Q    = 2 * BIG;
constexpr size_t OFF_K    = 3 * BIG;
constexpr size_t OFF_V    = 4 * BIG;
constexpr size_t OFF_PS   = 5 * BIG;
constexpr size_t OFF_PD   = OFF_PS + SMALLV;
constexpr size_t OFF_CSR  = OFF_PD + SMALLV;               // int2 per edge
constexpr size_t OFF_OFFS = OFF_CSR + 2 * (size_t)T_ * E_; // int offsets [RN+1]
constexpr size_t OFF_CUR  = OFF_OFFS + RN + 8;
constexpr size_t OFF_BS   = OFF_CUR + RN + 8;
constexpr size_t OFF_BIMG = OFF_BS + 512;                  // 8 mats x (16384 hi + 16384 lo) bf16
constexpr size_t POOL_SZ  = OFF_BIMG + 131072;

__device__ __align__(256) float g_pool[POOL_SZ];

// ---------------- weight conversion: 8 matrices -> row-major [k][n] bf16 hi/lo ----------------
// g: 0..1 = GAT layer (B[k][n] = W_s[ell][n>>4][k][n&15]); 2+ell*3+{0,1,2} = Q/K/V (B[k][n] = W[ell][k][n])
__global__ void prep_bconv(const float* __restrict__ Ws_, const float* __restrict__ Wq,
                           const float* __restrict__ Wk, const float* __restrict__ Wv,
                           __nv_bfloat16* __restrict__ Bimg) {
    int i = blockIdx.x * 256 + threadIdx.x;            // < 131072 = 8*16384
    int g = i >> 14, idx = i & 16383;
    int k = idx >> 7, n = idx & 127;
    float val;
    if (g < 2) {
        val = Ws_[g * 16384 + (n >> 4) * 2048 + k * 16 + (n & 15)];
    } else {
        int m = g - 2, ell = m / 3, sel = m % 3;
        const float* W = sel == 0 ? Wq : (sel == 1 ? Wk : Wv);
        val = W[ell * 16384 + k * 128 + n];
    }
    __nv_bfloat16 hi = __float2bfloat16_rn(val);
    __nv_bfloat16 lo = __float2bfloat16_rn(val - __bfloat162float(hi));
    Bimg[(size_t)g * 32768 + idx] = hi;
    Bimg[(size_t)g * 32768 + 16384 + idx] = lo;
}

// ---------------- tensor-core GEMM via wmma (HMMA; tcgen05 blocked by compile target) -------
// C_m[400000][128] = X[400000][128] @ W_m[128][128], m < nmats (A converted once, B cycled).
// Split-fp32: D = Ahi*Bhi + Ahi*Blo + Alo*Bhi. Inner loop: all B frags cached in registers,
// MMAs grouped by term so consecutive MMAs hit different accumulators (no dependency chain).
constexpr int LDA = 136;                               // padded smem leading dim (bf16 elems)
constexpr int GEMM_SMEM_BYTES = (2 * 64 * LDA + 2 * 128 * LDA) * 2;  // 104448

__global__ __launch_bounds__(256, 2) void gemm_w(const float* __restrict__ X,
                                                 const __nv_bfloat16* __restrict__ Bm,
                                                 float* __restrict__ C0,
                                                 float* __restrict__ C1,
                                                 float* __restrict__ C2,
                                                 int xmode, int nmats) {
    extern __shared__ __nv_bfloat16 sm[];
    __nv_bfloat16* Ah = sm;
    __nv_bfloat16* Al = Ah + 64 * LDA;
    __nv_bfloat16* Bh = Al + 64 * LDA;
    __nv_bfloat16* Bl = Bh + 128 * LDA;
    const int tid = threadIdx.x;

    // A tile: load 64 rows fp32, convert to bf16 hi/lo (once per CTA)
    size_t row0 = (size_t)blockIdx.x * 64;
    for (int p = tid; p < 2048; p += 256) {            // p = r*32 + c4
        int r = p >> 5, c4 = p & 31;
        size_t gr = row0 + r;
        size_t srow = xmode ? ((gr % N_) * T_ + gr / N_) : gr;
        float4 v = ((const float4*)X)[srow * 32 + c4];
        __nv_bfloat16 h0 = __float2bfloat16_rn(v.x), h1 = __float2bfloat16_rn(v.y);
        __nv_bfloat16 h2 = __float2bfloat16_rn(v.z), h3 = __float2bfloat16_rn(v.w);
        __nv_bfloat162 hp0(h0, h1), hp1(h2, h3);
        __nv_bfloat162 lp0 = __floats2bfloat162_rn(v.x - __bfloat162float(h0),
                                                   v.y - __bfloat162float(h1));
        __nv_bfloat162 lp1 = __floats2bfloat162_rn(v.z - __bfloat162float(h2),
                                                   v.w - __bfloat162float(h3));
        uint2 hw, lw;
        hw.x = *(uint32_t*)&hp0; hw.y = *(uint32_t*)&hp1;
        lw.x = *(uint32_t*)&lp0; lw.y = *(uint32_t*)&lp1;
        *(uint2*)(Ah + r * LDA + c4 * 4) = hw;
        *(uint2*)(Al + r * LDA + c4 * 4) = lw;
    }

    // warp w: row-block rb = w>>1 (16 rows), col-half ch = w&1 (4 x 16-col blocks)
    int w = tid >> 5;
    int rb = w >> 1, ch = w & 1;

    for (int m = 0; m < nmats; m++) {
        // B_m hi/lo -> smem (row-major [k][128], padded rows)
        const uint4* bsrc = (const uint4*)(Bm + (size_t)m * 32768);
        for (int p = tid; p < 2048; p += 256) {        // p = k*16 + c (8 bf16 per uint4)
            int k = p >> 4, c = p & 15;
            *(uint4*)(Bh + k * LDA + c * 8) = bsrc[p];
            *(uint4*)(Bl + k * LDA + c * 8) = bsrc[2048 + p];
        }
        __syncthreads();

        wmma::fragment<wmma::accumulator, 16, 16, 16, float> acc[4];
#pragma unroll
        for (int j = 0; j < 4; j++) wmma::fill_fragment(acc[j], 0.f);

#pragma unroll
        for (int ks = 0; ks < 8; ks++) {
            wmma::fragment<wmma::matrix_a, 16, 16, 16, __nv_bfloat16, wmma::row_major> ah, al;
            wmma::load_matrix_sync(ah, Ah + (rb * 16) * LDA + ks * 16, LDA);
            wmma::load_matrix_sync(al, Al + (rb * 16) * LDA + ks * 16, LDA);
            wmma::fragment<wmma::matrix_b, 16, 16, 16, __nv_bfloat16, wmma::row_major> bh[4], bl[4];
#pragma unroll
            for (int cb = 0; cb < 4; cb++) {
                int col = ch * 64 + cb * 16;
                wmma::load_matrix_sync(bh[cb], Bh + (ks * 16) * LDA + col, LDA);
                wmma::load_matrix_sync(bl[cb], Bl + (ks * 16) * LDA + col, LDA);
            }
            // grouped by term: consecutive MMAs use different accumulators
#pragma unroll
            for (int cb = 0; cb < 4; cb++) wmma::mma_sync(acc[cb], ah, bh[cb], acc[cb]);
#pragma unroll
            for (int cb = 0; cb < 4; cb++) wmma::mma_sync(acc[cb], ah, bl[cb], acc[cb]);
#pragma unroll
            for (int cb = 0; cb < 4; cb++) wmma::mma_sync(acc[cb], al, bh[cb], acc[cb]);
        }

        float* Cm = (m == 0) ? C0 : (m == 1 ? C1 : C2);
#pragma unroll
        for (int cb = 0; cb < 4; cb++) {
            wmma::store_matrix_sync(Cm + (row0 + rb * 16) * 128 + ch * 64 + cb * 16,
                                    acc[cb], 128, wmma::mem_row_major);
        }
        if (m + 1 < nmats) __syncthreads();            // protect B smem before next fill
    }
}

// ---------------- CSR build ----------------
__global__ void zero_int(int* __restrict__ p, int n) {
    int i = blockIdx.x * 256 + threadIdx.x;
    if (i < n) p[i] = 0;
}

__global__ void hist_kernel(const int* __restrict__ eidx, int* __restrict__ counts) {
    int gid = blockIdx.x * 256 + threadIdx.x;
    int t = gid / E_, e = gid - t * E_;
    int src = eidx[(size_t)t * 2 * E_ + e];
    atomicAdd(counts + t * N_ + src, 1);
}

__global__ __launch_bounds__(1024) void scan_block(const int* __restrict__ counts,
                                                   int* __restrict__ offs,
                                                   int* __restrict__ bsum) {
    __shared__ int s[1024];
    int tid = threadIdx.x;
    int i = blockIdx.x * 1024 + tid;
    int v = (i < (int)RN) ? counts[i] : 0;
    s[tid] = v;
    __syncthreads();
#pragma unroll
    for (int off = 1; off < 1024; off <<= 1) {
        int x = (tid >= off) ? s[tid - off] : 0;
        __syncthreads();
        s[tid] += x;
        __syncthreads();
    }
    if (i < (int)RN) offs[i] = s[tid] - v;
    if (tid == 1023) bsum[blockIdx.x] = s[1023];
}

__global__ __launch_bounds__(512) void scan_bsum(int* __restrict__ bsum, int nb) {
    __shared__ int s[512];
    int tid = threadIdx.x;
    int v = (tid < nb) ? bsum[tid] : 0;
    s[tid] = v;
    __syncthreads();
#pragma unroll
    for (int off = 1; off < 512; off <<= 1) {
        int x = (tid >= off) ? s[tid - off] : 0;
        __syncthreads();
        s[tid] += x;
        __syncthreads();
    }
    if (tid < nb) bsum[tid] = s[tid] - v;
}

__global__ void scan_add(int* __restrict__ offs, const int* __restrict__ bsum,
                         int* __restrict__ cursor) {
    int i = blockIdx.x * 256 + threadIdx.x;
    if (i < (int)RN) {
        int o = offs[i] + bsum[i >> 10];
        offs[i] = o;
        cursor[i] = o;
        if (i == 0) offs[RN] = T_ * E_;
    }
}

__global__ void scatter_kernel(const int* __restrict__ eidx, const float* __restrict__ evals,
                               int* __restrict__ cursor, int2* __restrict__ csr) {
    int gid = blockIdx.x * 256 + threadIdx.x;
    int t = gid / E_, e = gid - t * E_;
    const int* ei = eidx + (size_t)t * 2 * E_;
    int src = ei[e];
    int dst = ei[E_ + e];
    int pos = atomicAdd(cursor + t * N_ + src, 1);
    csr[pos] = make_int2(dst, __float_as_int(evals[(size_t)t * E_ + e]));
}

// ---------------- ps/pd ----------------
__global__ __launch_bounds__(256) void pspd_kernel(const float* __restrict__ H,
                                                   const float* __restrict__ a,
                                                   float* __restrict__ ps, float* __restrict__ pd) {
    int r = blockIdx.x * 8 + (threadIdx.x >> 5);
    int lane = threadIdx.x & 31;
    float4 hv = ((const float4*)H)[(size_t)r * 32 + lane];
    int h = lane >> 2, fo = (lane & 3) * 4;
    const float* ah = a + h * 32;
    float4 av = *(const float4*)(ah + fo);
    float4 bv = *(const float4*)(ah + 16 + fo);
    float s = hv.x * av.x + hv.y * av.y + hv.z * av.z + hv.w * av.w;
    float d = hv.x * bv.x + hv.y * bv.y + hv.z * bv.z + hv.w * bv.w;
    s += __shfl_xor_sync(0xffffffffu, s, 1);
    s += __shfl_xor_sync(0xffffffffu, s, 2);
    d += __shfl_xor_sync(0xffffffffu, d, 1);
    d += __shfl_xor_sync(0xffffffffu, d, 2);
    if ((lane & 3) == 0) { ps[r * 8 + h] = s; pd[r * 8 + h] = d; }
}

// ---------------- fused GAT aggregate + normalize + ELU + transpose + Wp -> ti ----------------
__global__ __launch_bounds__(256) void gat_agg_kernel(const int* __restrict__ offs,
                                                      const int2* __restrict__ csr,
                                                      const float* __restrict__ H,
                                                      const float* __restrict__ ps,
                                                      const float* __restrict__ pd,
                                                      const float* __restrict__ Wp,
                                                      float* __restrict__ ti) {
    int r = blockIdx.x * 8 + (threadIdx.x >> 5);
    int lane = threadIdx.x & 31;
    int h = lane >> 2;
    int t = r / N_;
    int n = r - t * N_;
    int beg = offs[r], end = offs[r + 1];
    float psv = __ldg(ps + r * 8 + h);
    float4 acc = make_float4(0.f, 0.f, 0.f, 0.f);
    float esum = 0.f;
    const int tbase = t * N_;

    int2 cur = csr[beg];
    for (int j = beg; j < end; j++) {
        int2 nxt = make_int2(0, 0);
        if (j + 1 < end) nxt = csr[j + 1];
        int rd = tbase + cur.x;
        float w = __int_as_float(cur.y);
        float pdv = __ldg(pd + rd * 8 + h);
        float4 hv = ((const float4*)H)[(size_t)rd * 32 + lane];
        float sc = w * (psv + pdv);
        sc = sc > 0.f ? sc : 0.2f * sc;
        float ev = __expf(sc);
        esum += ev;
        acc.x += ev * hv.x;
        acc.y += ev * hv.y;
        acc.z += ev * hv.z;
        acc.w += ev * hv.w;
        cur = nxt;
    }
    float inv = 1.f / esum;
    float4 wp = ((const float4*)Wp)[t * 32 + lane];
    float vx = acc.x * inv, vy = acc.y * inv, vz = acc.z * inv, vw = acc.w * inv;
    vx = vx > 0.f ? vx : expm1f(vx);
    vy = vy > 0.f ? vy : expm1f(vy);
    vz = vz > 0.f ? vz : expm1f(vz);
    vw = vw > 0.f ? vw : expm1f(vw);
    float4 o = make_float4(vx + wp.x, vy + wp.y, vz + wp.z, vw + wp.w);
    ((float4*)ti)[((size_t)n * T_ + t) * 32 + lane] = o;
}

// ---------------- temporal attention ----------------
__global__ __launch_bounds__(256) void attn_kernel(const float* __restrict__ Q,
                                                   const float* __restrict__ K,
                                                   const float* __restrict__ V,
                                                   const float* __restrict__ ti,
                                                   float* __restrict__ out) {
    __shared__ float sb[8][384];
    int warp = threadIdx.x >> 5, lane = threadIdx.x & 31;
    int task = blockIdx.x * 8 + warp;
    int n = task >> 3, h = task & 7;
    int t4 = lane >> 2;
    int r4 = (n * T_ + t4) * 32 + h * 4 + (lane & 3);
    float* sq = sb[warp];
    float* sk = sq + 128;
    float* sv = sq + 256;
    ((float4*)sq)[lane] = ((const float4*)Q)[(size_t)r4];
    ((float4*)sk)[lane] = ((const float4*)K)[(size_t)r4];
    ((float4*)sv)[lane] = ((const float4*)V)[(size_t)r4];
    __syncwarp();
    if (lane < 8) {
        int t = lane;
        float q[16];
#pragma unroll
        for (int j = 0; j < 16; j++) q[j] = sq[t * 16 + j];
        float p[8];
        float mx = -1e30f;
#pragma unroll
        for (int s = 0; s < 8; s++) {
            float d = 0.f;
#pragma unroll
            for (int j = 0; j < 16; j++) d += q[j] * sk[s * 16 + j];
            d *= 0.25f;
            p[s] = d;
            if (s <= t && d > mx) mx = d;
        }
        float sum = 0.f;
#pragma unroll
        for (int s = 0; s < 8; s++) {
            float e = (s <= t) ? __expf(p[s] - mx) : 0.f;
            p[s] = e;
            sum += e;
        }
        float inv = 1.f / sum;
        float o[16];
#pragma unroll
        for (int j = 0; j < 16; j++) o[j] = 0.f;
#pragma unroll
        for (int s = 0; s < 8; s++) {
            float e = p[s];
#pragma unroll
            for (int j = 0; j < 16; j++) o[j] += e * sv[s * 16 + j];
        }
        size_t base = (size_t)(n * T_ + t) * 128 + h * 16;
#pragma unroll
        for (int j4 = 0; j4 < 4; j4++) {
            float4 tv = ((const float4*)(ti + base))[j4];
            float4 ov = make_float4(o[j4 * 4 + 0] * inv + tv.x,
                                    o[j4 * 4 + 1] * inv + tv.y,
                                    o[j4 * 4 + 2] * inv + tv.z,
                                    o[j4 * 4 + 3] * inv + tv.w);
            ((float4*)(out + base))[j4] = ov;
        }
    }
}

// ---------------- host ----------------
extern "C" void kernel_launch(void* const* d_in, const int* in_sizes, int n_in,
                              void* d_out, int out_size) {
    const float* features  = (const float*)d_in[0];
    const int*   edge_idx  = (const int*)d_in[1];
    const float* edge_vals = (const float*)d_in[2];
    const float* W_s       = (const float*)d_in[3];
    const float* a_s       = (const float*)d_in[4];
    const float* Wq        = (const float*)d_in[5];
    const float* Wkk       = (const float*)d_in[6];
    const float* Wv        = (const float*)d_in[7];
    const float* Wp        = (const float*)d_in[8];
    float* out = (float*)d_out;

    float* pool = nullptr;
    cudaGetSymbolAddress((void**)&pool, g_pool);
    float* H   = pool + OFF_H;
    float* TI  = pool + OFF_TI;
    float* Qb  = pool + OFF_Q;
    float* Kb  = pool + OFF_K;
    float* Vb  = pool + OFF_V;
    float* ps  = pool + OFF_PS;
    float* pd  = pool + OFF_PD;
    int2*  csr    = (int2*)(pool + OFF_CSR);
    int*   offs   = (int*)(pool + OFF_OFFS);
    int*   cursor = (int*)(pool + OFF_CUR);
    int*   bsum   = (int*)(pool + OFF_BS);
    __nv_bfloat16* Bimg = (__nv_bfloat16*)(pool + OFF_BIMG);

    cudaFuncSetAttribute(gemm_w, cudaFuncAttributeMaxDynamicSharedMemorySize, GEMM_SMEM_BYTES);

    const int nb_scan = (int)((RN + 1023) / 1024);

    // launch order: capture index 3 = gemm_w (ncu profiles ~index 3)
    prep_bconv<<<512, 256>>>(W_s, Wq, Wkk, Wv, Bimg);                       // 0
    zero_int<<<(int)((RN + 255) / 256), 256>>>(cursor, (int)RN);            // 1
    hist_kernel<<<(T_ * E_) / 256, 256>>>(edge_idx, cursor);                // 2
    gemm_w<<<6250, 256, GEMM_SMEM_BYTES>>>(features, Bimg, H, nullptr, nullptr, 0, 1);  // 3
    scan_block<<<nb_scan, 1024>>>(cursor, offs, bsum);                      // 4
    scan_bsum<<<1, 512>>>(bsum, nb_scan);                                   // 5
    scan_add<<<(int)((RN + 255) / 256), 256>>>(offs, bsum, cursor);         // 6
    scatter_kernel<<<(T_ * E_) / 256, 256>>>(edge_idx, edge_vals, cursor, csr);  // 7

    for (int ell = 0; ell < L_; ell++) {
        if (ell) {
            gemm_w<<<6250, 256, GEMM_SMEM_BYTES>>>((const float*)out,
                                                   Bimg + (size_t)ell * 32768,
                                                   H, nullptr, nullptr, 1, 1);
        }
        pspd_kernel<<<50000, 256>>>(H, a_s + ell * 256, ps, pd);
        gat_agg_kernel<<<50000, 256>>>(offs, csr, H, ps, pd, Wp + ell * (T_ * D_), TI);
        // fused Q,K,V: A loaded/converted once, 3 B matrices cycled through smem
        gemm_w<<<6250, 256, GEMM_SMEM_BYTES>>>(TI, Bimg + (size_t)(2 + ell * 3) * 32768,
                                               Qb, Kb, Vb, 0, 3);
        attn_kernel<<<50000, 256>>>(Qb, Kb, Vb, TI, out);
    }
}

// round 10
// speedup vs baseline: 1.5148x; 1.5148x over previous
#include <cuda_runtime.h>
#include <cuda_bf16.h>
#include <mma.h>
#include <cstdint>

using namespace nvcuda;

#define T_ 8
#define N_ 50000
#define D_ 128
#define E_ 800000
#define L_ 2
#define SH_ 8
#define FH_ 16

// ---------------- scratch pool (static device memory; no allocs) ----------------
constexpr size_t BIG    = (size_t)T_ * N_ * D_;    // 51,200,000 floats
constexpr size_t SMALLV = (size_t)T_ * N_ * SH_;   // 3,200,000 floats
constexpr size_t RN     = (size_t)T_ * N_;         // 400,000 rows
constexpr size_t OFF_H    = 0;
constexpr size_t OFF_TI   = BIG;
constexpr size_t OFF_Q    = 2 * BIG;
constexpr size_t OFF_K    = 3 * BIG;
constexpr size_t OFF_V    = 4 * BIG;
constexpr size_t OFF_PS   = 5 * BIG;
constexpr size_t OFF_PD   = OFF_PS + SMALLV;
constexpr size_t OFF_CSR  = OFF_PD + SMALLV;               // int2 per edge
constexpr size_t OFF_OFFS = OFF_CSR + 2 * (size_t)T_ * E_; // int offsets [RN+1]
constexpr size_t OFF_CUR  = OFF_OFFS + RN + 8;
constexpr size_t OFF_BS   = OFF_CUR + RN + 8;
constexpr size_t OFF_BIMG = OFF_BS + 512;                  // 8 mats x (16384 hi + 16384 lo) bf16
constexpr size_t POOL_SZ  = OFF_BIMG + 131072;

__device__ __align__(256) float g_pool[POOL_SZ];

// ---------------- weight conversion: 8 matrices -> row-major [k][n] bf16 hi/lo ----------------
// g: 0..1 = GAT layer (B[k][n] = W_s[ell][n>>4][k][n&15]); 2+ell*3+{0,1,2} = Q/K/V (B[k][n] = W[ell][k][n])
__global__ void prep_bconv(const float* __restrict__ Ws_, const float* __restrict__ Wq,
                           const float* __restrict__ Wk, const float* __restrict__ Wv,
                           __nv_bfloat16* __restrict__ Bimg) {
    int i = blockIdx.x * 256 + threadIdx.x;            // < 131072 = 8*16384
    int g = i >> 14, idx = i & 16383;
    int k = idx >> 7, n = idx & 127;
    float val;
    if (g < 2) {
        val = Ws_[g * 16384 + (n >> 4) * 2048 + k * 16 + (n & 15)];
    } else {
        int m = g - 2, ell = m / 3, sel = m % 3;
        const float* W = sel == 0 ? Wq : (sel == 1 ? Wk : Wv);
        val = W[ell * 16384 + k * 128 + n];
    }
    __nv_bfloat16 hi = __float2bfloat16_rn(val);
    __nv_bfloat16 lo = __float2bfloat16_rn(val - __bfloat162float(hi));
    Bimg[(size_t)g * 32768 + idx] = hi;
    Bimg[(size_t)g * 32768 + 16384 + idx] = lo;
}

// ---------------- tensor-core GEMM via wmma (HMMA; tcgen05 blocked by compile target) -------
// C_m[400000][128] = X[400000][128] @ W_m[128][128], m < nmats (A converted once, B cycled).
// Split-fp32: D = Ahi*Bhi + Ahi*Blo + Alo*Bhi.
// Inner loop: 2x2 interleave — only 4 B fragments live (no spills), dependent MMAs 2 apart.
constexpr int LDA = 136;                               // padded smem leading dim (bf16 elems)
constexpr int GEMM_SMEM_BYTES = (2 * 64 * LDA + 2 * 128 * LDA) * 2;  // 104448

__global__ __launch_bounds__(256, 2) void gemm_w(const float* __restrict__ X,
                                                 const __nv_bfloat16* __restrict__ Bm,
                                                 float* __restrict__ C0,
                                                 float* __restrict__ C1,
                                                 float* __restrict__ C2,
                                                 int xmode, int nmats) {
    extern __shared__ __nv_bfloat16 sm[];
    __nv_bfloat16* Ah = sm;
    __nv_bfloat16* Al = Ah + 64 * LDA;
    __nv_bfloat16* Bh = Al + 64 * LDA;
    __nv_bfloat16* Bl = Bh + 128 * LDA;
    const int tid = threadIdx.x;

    // A tile: load 64 rows fp32, convert to bf16 hi/lo (once per CTA)
    size_t row0 = (size_t)blockIdx.x * 64;
    for (int p = tid; p < 2048; p += 256) {            // p = r*32 + c4
        int r = p >> 5, c4 = p & 31;
        size_t gr = row0 + r;
        size_t srow = xmode ? ((gr % N_) * T_ + gr / N_) : gr;
        float4 v = ((const float4*)X)[srow * 32 + c4];
        __nv_bfloat16 h0 = __float2bfloat16_rn(v.x), h1 = __float2bfloat16_rn(v.y);
        __nv_bfloat16 h2 = __float2bfloat16_rn(v.z), h3 = __float2bfloat16_rn(v.w);
        __nv_bfloat162 hp0(h0, h1), hp1(h2, h3);
        __nv_bfloat162 lp0 = __floats2bfloat162_rn(v.x - __bfloat162float(h0),
                                                   v.y - __bfloat162float(h1));
        __nv_bfloat162 lp1 = __floats2bfloat162_rn(v.z - __bfloat162float(h2),
                                                   v.w - __bfloat162float(h3));
        uint2 hw, lw;
        hw.x = *(uint32_t*)&hp0; hw.y = *(uint32_t*)&hp1;
        lw.x = *(uint32_t*)&lp0; lw.y = *(uint32_t*)&lp1;
        *(uint2*)(Ah + r * LDA + c4 * 4) = hw;
        *(uint2*)(Al + r * LDA + c4 * 4) = lw;
    }

    // warp w: row-block rb = w>>1 (16 rows), col-half ch = w&1 (4 x 16-col blocks)
    int w = tid >> 5;
    int rb = w >> 1, ch = w & 1;

    for (int m = 0; m < nmats; m++) {
        // B_m hi/lo -> smem (row-major [k][128], padded rows)
        const uint4* bsrc = (const uint4*)(Bm + (size_t)m * 32768);
        for (int p = tid; p < 2048; p += 256) {        // p = k*16 + c (8 bf16 per uint4)
            int k = p >> 4, c = p & 15;
            *(uint4*)(Bh + k * LDA + c * 8) = bsrc[p];
            *(uint4*)(Bl + k * LDA + c * 8) = bsrc[2048 + p];
        }
        __syncthreads();

        wmma::fragment<wmma::accumulator, 16, 16, 16, float> acc[4];
#pragma unroll
        for (int j = 0; j < 4; j++) wmma::fill_fragment(acc[j], 0.f);

#pragma unroll
        for (int ks = 0; ks < 8; ks++) {
            wmma::fragment<wmma::matrix_a, 16, 16, 16, __nv_bfloat16, wmma::row_major> ah, al;
            wmma::load_matrix_sync(ah, Ah + (rb * 16) * LDA + ks * 16, LDA);
            wmma::load_matrix_sync(al, Al + (rb * 16) * LDA + ks * 16, LDA);
#pragma unroll
            for (int half = 0; half < 2; half++) {
                // only 4 B fragments live at once; MMAs alternate between 2 accumulators
                wmma::fragment<wmma::matrix_b, 16, 16, 16, __nv_bfloat16, wmma::row_major>
                    b0h, b1h, b0l, b1l;
                int col = ch * 64 + half * 32;
                wmma::load_matrix_sync(b0h, Bh + (ks * 16) * LDA + col, LDA);
                wmma::load_matrix_sync(b1h, Bh + (ks * 16) * LDA + col + 16, LDA);
                wmma::load_matrix_sync(b0l, Bl + (ks * 16) * LDA + col, LDA);
                wmma::load_matrix_sync(b1l, Bl + (ks * 16) * LDA + col + 16, LDA);
                int a0 = half * 2, a1 = half * 2 + 1;
                wmma::mma_sync(acc[a0], ah, b0h, acc[a0]);
                wmma::mma_sync(acc[a1], ah, b1h, acc[a1]);
                wmma::mma_sync(acc[a0], ah, b0l, acc[a0]);
                wmma::mma_sync(acc[a1], ah, b1l, acc[a1]);
                wmma::mma_sync(acc[a0], al, b0h, acc[a0]);
                wmma::mma_sync(acc[a1], al, b1h, acc[a1]);
            }
        }

        float* Cm = (m == 0) ? C0 : (m == 1 ? C1 : C2);
#pragma unroll
        for (int cb = 0; cb < 4; cb++) {
            wmma::store_matrix_sync(Cm + (row0 + rb * 16) * 128 + ch * 64 + cb * 16,
                                    acc[cb], 128, wmma::mem_row_major);
        }
        if (m + 1 < nmats) __syncthreads();            // protect B smem before next fill
    }
}

// ---------------- CSR build ----------------
__global__ void zero_int(int* __restrict__ p, int n) {
    int i = blockIdx.x * 256 + threadIdx.x;
    if (i < n) p[i] = 0;
}

__global__ void hist_kernel(const int* __restrict__ eidx, int* __restrict__ counts) {
    int gid = blockIdx.x * 256 + threadIdx.x;
    int t = gid / E_, e = gid - t * E_;
    int src = eidx[(size_t)t * 2 * E_ + e];
    atomicAdd(counts + t * N_ + src, 1);
}

__global__ __launch_bounds__(1024) void scan_block(const int* __restrict__ counts,
                                                   int* __restrict__ offs,
                                                   int* __restrict__ bsum) {
    __shared__ int s[1024];
    int tid = threadIdx.x;
    int i = blockIdx.x * 1024 + tid;
    int v = (i < (int)RN) ? counts[i] : 0;
    s[tid] = v;
    __syncthreads();
#pragma unroll
    for (int off = 1; off < 1024; off <<= 1) {
        int x = (tid >= off) ? s[tid - off] : 0;
        __syncthreads();
        s[tid] += x;
        __syncthreads();
    }
    if (i < (int)RN) offs[i] = s[tid] - v;
    if (tid == 1023) bsum[blockIdx.x] = s[1023];
}

__global__ __launch_bounds__(512) void scan_bsum(int* __restrict__ bsum, int nb) {
    __shared__ int s[512];
    int tid = threadIdx.x;
    int v = (tid < nb) ? bsum[tid] : 0;
    s[tid] = v;
    __syncthreads();
#pragma unroll
    for (int off = 1; off < 512; off <<= 1) {
        int x = (tid >= off) ? s[tid - off] : 0;
        __syncthreads();
        s[tid] += x;
        __syncthreads();
    }
    if (tid < nb) bsum[tid] = s[tid] - v;
}

__global__ void scan_add(int* __restrict__ offs, const int* __restrict__ bsum,
                         int* __restrict__ cursor) {
    int i = blockIdx.x * 256 + threadIdx.x;
    if (i < (int)RN) {
        int o = offs[i] + bsum[i >> 10];
        offs[i] = o;
        cursor[i] = o;
        if (i == 0) offs[RN] = T_ * E_;
    }
}

__global__ void scatter_kernel(const int* __restrict__ eidx, const float* __restrict__ evals,
                               int* __restrict__ cursor, int2* __restrict__ csr) {
    int gid = blockIdx.x * 256 + threadIdx.x;
    int t = gid / E_, e = gid - t * E_;
    const int* ei = eidx + (size_t)t * 2 * E_;
    int src = ei[e];
    int dst = ei[E_ + e];
    int pos = atomicAdd(cursor + t * N_ + src, 1);
    csr[pos] = make_int2(dst, __float_as_int(evals[(size_t)t * E_ + e]));
}

// ---------------- ps/pd ----------------
__global__ __launch_bounds__(256) void pspd_kernel(const float* __restrict__ H,
                                                   const float* __restrict__ a,
                                                   float* __restrict__ ps, float* __restrict__ pd) {
    int r = blockIdx.x * 8 + (threadIdx.x >> 5);
    int lane = threadIdx.x & 31;
    float4 hv = ((const float4*)H)[(size_t)r * 32 + lane];
    int h = lane >> 2, fo = (lane & 3) * 4;
    const float* ah = a + h * 32;
    float4 av = *(const float4*)(ah + fo);
    float4 bv = *(const float4*)(ah + 16 + fo);
    float s = hv.x * av.x + hv.y * av.y + hv.z * av.z + hv.w * av.w;
    float d = hv.x * bv.x + hv.y * bv.y + hv.z * bv.z + hv.w * bv.w;
    s += __shfl_xor_sync(0xffffffffu, s, 1);
    s += __shfl_xor_sync(0xffffffffu, s, 2);
    d += __shfl_xor_sync(0xffffffffu, d, 1);
    d += __shfl_xor_sync(0xffffffffu, d, 2);
    if ((lane & 3) == 0) { ps[r * 8 + h] = s; pd[r * 8 + h] = d; }
}

// ---------------- fused GAT aggregate + normalize + ELU + transpose + Wp -> ti ----------------
__global__ __launch_bounds__(256) void gat_agg_kernel(const int* __restrict__ offs,
                                                      const int2* __restrict__ csr,
                                                      const float* __restrict__ H,
                                                      const float* __restrict__ ps,
                                                      const float* __restrict__ pd,
                                                      const float* __restrict__ Wp,
                                                      float* __restrict__ ti) {
    int r = blockIdx.x * 8 + (threadIdx.x >> 5);
    int lane = threadIdx.x & 31;
    int h = lane >> 2;
    int t = r / N_;
    int n = r - t * N_;
    int beg = offs[r], end = offs[r + 1];
    float psv = __ldg(ps + r * 8 + h);
    float4 acc = make_float4(0.f, 0.f, 0.f, 0.f);
    float esum = 0.f;
    const int tbase = t * N_;

    int2 cur = csr[beg];
    for (int j = beg; j < end; j++) {
        int2 nxt = make_int2(0, 0);
        if (j + 1 < end) nxt = csr[j + 1];
        int rd = tbase + cur.x;
        float w = __int_as_float(cur.y);
        float pdv = __ldg(pd + rd * 8 + h);
        float4 hv = ((const float4*)H)[(size_t)rd * 32 + lane];
        float sc = w * (psv + pdv);
        sc = sc > 0.f ? sc : 0.2f * sc;
        float ev = __expf(sc);
        esum += ev;
        acc.x += ev * hv.x;
        acc.y += ev * hv.y;
        acc.z += ev * hv.z;
        acc.w += ev * hv.w;
        cur = nxt;
    }
    float inv = 1.f / esum;
    float4 wp = ((const float4*)Wp)[t * 32 + lane];
    float vx = acc.x * inv, vy = acc.y * inv, vz = acc.z * inv, vw = acc.w * inv;
    vx = vx > 0.f ? vx : expm1f(vx);
    vy = vy > 0.f ? vy : expm1f(vy);
    vz = vz > 0.f ? vz : expm1f(vz);
    vw = vw > 0.f ? vw : expm1f(vw);
    float4 o = make_float4(vx + wp.x, vy + wp.y, vz + wp.z, vw + wp.w);
    ((float4*)ti)[((size_t)n * T_ + t) * 32 + lane] = o;
}

// ---------------- temporal attention ----------------
__global__ __launch_bounds__(256) void attn_kernel(const float* __restrict__ Q,
                                                   const float* __restrict__ K,
                                                   const float* __restrict__ V,
                                                   const float* __restrict__ ti,
                                                   float* __restrict__ out) {
    __shared__ float sb[8][384];
    int warp = threadIdx.x >> 5, lane = threadIdx.x & 31;
    int task = blockIdx.x * 8 + warp;
    int n = task >> 3, h = task & 7;
    int t4 = lane >> 2;
    int r4 = (n * T_ + t4) * 32 + h * 4 + (lane & 3);
    float* sq = sb[warp];
    float* sk = sq + 128;
    float* sv = sq + 256;
    ((float4*)sq)[lane] = ((const float4*)Q)[(size_t)r4];
    ((float4*)sk)[lane] = ((const float4*)K)[(size_t)r4];
    ((float4*)sv)[lane] = ((const float4*)V)[(size_t)r4];
    __syncwarp();
    if (lane < 8) {
        int t = lane;
        float q[16];
#pragma unroll
        for (int j = 0; j < 16; j++) q[j] = sq[t * 16 + j];
        float p[8];
        float mx = -1e30f;
#pragma unroll
        for (int s = 0; s < 8; s++) {
            float d = 0.f;
#pragma unroll
            for (int j = 0; j < 16; j++) d += q[j] * sk[s * 16 + j];
            d *= 0.25f;
            p[s] = d;
            if (s <= t && d > mx) mx = d;
        }
        float sum = 0.f;
#pragma unroll
        for (int s = 0; s < 8; s++) {
            float e = (s <= t) ? __expf(p[s] - mx) : 0.f;
            p[s] = e;
            sum += e;
        }
        float inv = 1.f / sum;
        float o[16];
#pragma unroll
        for (int j = 0; j < 16; j++) o[j] = 0.f;
#pragma unroll
        for (int s = 0; s < 8; s++) {
            float e = p[s];
#pragma unroll
            for (int j = 0; j < 16; j++) o[j] += e * sv[s * 16 + j];
        }
        size_t base = (size_t)(n * T_ + t) * 128 + h * 16;
#pragma unroll
        for (int j4 = 0; j4 < 4; j4++) {
            float4 tv = ((const float4*)(ti + base))[j4];
            float4 ov = make_float4(o[j4 * 4 + 0] * inv + tv.x,
                                    o[j4 * 4 + 1] * inv + tv.y,
                                    o[j4 * 4 + 2] * inv + tv.z,
                                    o[j4 * 4 + 3] * inv + tv.w);
            ((float4*)(out + base))[j4] = ov;
        }
    }
}

// ---------------- host ----------------
extern "C" void kernel_launch(void* const* d_in, const int* in_sizes, int n_in,
                              void* d_out, int out_size) {
    const float* features  = (const float*)d_in[0];
    const int*   edge_idx  = (const int*)d_in[1];
    const float* edge_vals = (const float*)d_in[2];
    const float* W_s       = (const float*)d_in[3];
    const float* a_s       = (const float*)d_in[4];
    const float* Wq        = (const float*)d_in[5];
    const float* Wkk       = (const float*)d_in[6];
    const float* Wv        = (const float*)d_in[7];
    const float* Wp        = (const float*)d_in[8];
    float* out = (float*)d_out;

    float* pool = nullptr;
    cudaGetSymbolAddress((void**)&pool, g_pool);
    float* H   = pool + OFF_H;
    float* TI  = pool + OFF_TI;
    float* Qb  = pool + OFF_Q;
    float* Kb  = pool + OFF_K;
    float* Vb  = pool + OFF_V;
    float* ps  = pool + OFF_PS;
    float* pd  = pool + OFF_PD;
    int2*  csr    = (int2*)(pool + OFF_CSR);
    int*   offs   = (int*)(pool + OFF_OFFS);
    int*   cursor = (int*)(pool + OFF_CUR);
    int*   bsum   = (int*)(pool + OFF_BS);
    __nv_bfloat16* Bimg = (__nv_bfloat16*)(pool + OFF_BIMG);

    cudaFuncSetAttribute(gemm_w, cudaFuncAttributeMaxDynamicSharedMemorySize, GEMM_SMEM_BYTES);

    const int nb_scan = (int)((RN + 1023) / 1024);

    // launch order: capture index 3 = gemm_w single-mat (ncu profiles ~index 3)
    prep_bconv<<<512, 256>>>(W_s, Wq, Wkk, Wv, Bimg);                       // 0
    zero_int<<<(int)((RN + 255) / 256), 256>>>(cursor, (int)RN);            // 1
    hist_kernel<<<(T_ * E_) / 256, 256>>>(edge_idx, cursor);                // 2
    gemm_w<<<6250, 256, GEMM_SMEM_BYTES>>>(features, Bimg, H, nullptr, nullptr, 0, 1);  // 3
    scan_block<<<nb_scan, 1024>>>(cursor, offs, bsum);                      // 4
    scan_bsum<<<1, 512>>>(bsum, nb_scan);                                   // 5
    scan_add<<<(int)((RN + 255) / 256), 256>>>(offs, bsum, cursor);         // 6
    scatter_kernel<<<(T_ * E_) / 256, 256>>>(edge_idx, edge_vals, cursor, csr);  // 7

    for (int ell = 0; ell < L_; ell++) {
        if (ell) {
            gemm_w<<<6250, 256, GEMM_SMEM_BYTES>>>((const float*)out,
                                                   Bimg + (size_t)ell * 32768,
                                                   H, nullptr, nullptr, 1, 1);
        }
        pspd_kernel<<<50000, 256>>>(H, a_s + ell * 256, ps, pd);
        gat_agg_kernel<<<50000, 256>>>(offs, csr, H, ps, pd, Wp + ell * (T_ * D_), TI);
        // fused Q,K,V: A loaded/converted once, 3 B matrices cycled through smem
        gemm_w<<<6250, 256, GEMM_SMEM_BYTES>>>(TI, Bimg + (size_t)(2 + ell * 3) * 32768,
                                               Qb, Kb, Vb, 0, 3);
        attn_kernel<<<50000, 256>>>(Qb, Kb, Vb, TI, out);
    }
}